// round 2
// baseline (speedup 1.0000x reference)
#include <cuda_runtime.h>
#include <math.h>

#define N_NODES 50000
#define N_EDGES 1600000
#define N_GRAPHS 64
#define DELTA_C 2.5749f
#define BN_EPS 1e-5f

// ---------------- scratch (__device__ globals; no allocation allowed) ----------------
__device__ float g_featA[N_NODES * 64];
__device__ float g_featB[N_NODES * 64];
__device__ float g_aggr[N_NODES * 256];      // [sums | maxs | means | var] per node
__device__ int   g_deg[N_NODES];
__device__ int   g_rowptr[N_NODES + 1];
__device__ int   g_cursor[N_NODES];
__device__ int   g_csrc[N_EDGES];
__device__ float g_Wt[3][256 * 192];         // transposed/packed mlp weights
__device__ float g_W1T[3][64 * 64];
__device__ float g_W2T[3][64 * 64];
__device__ float g_colsum[64];
__device__ float g_colsq[64];
__device__ float g_pool[N_GRAPHS * 64];

// ---------------- small utility kernels ----------------
__global__ void k_zero_deg() {
    int i = blockIdx.x * blockDim.x + threadIdx.x;
    if (i < N_NODES) g_deg[i] = 0;
}
__global__ void k_zero_stats() {
    int i = threadIdx.x;
    if (i < 64) { g_colsum[i] = 0.f; g_colsq[i] = 0.f; }
}
__global__ void k_zero_pool() {
    int i = blockIdx.x * blockDim.x + threadIdx.x;
    if (i < N_GRAPHS * 64) g_pool[i] = 0.f;
}

// ---------------- CSR build ----------------
__global__ void k_count(const int* __restrict__ dst) {
    int e = blockIdx.x * blockDim.x + threadIdx.x;
    if (e < N_EDGES) atomicAdd(&g_deg[dst[e]], 1);
}

__global__ void k_scan() {
    __shared__ int s[1024];
    int t = threadIdx.x;
    int offset = 0;
    for (int base = 0; base < N_NODES; base += 1024) {
        int idx = base + t;
        int v = (idx < N_NODES) ? g_deg[idx] : 0;
        __syncthreads();
        s[t] = v;
        __syncthreads();
        for (int d = 1; d < 1024; d <<= 1) {
            int add = (t >= d) ? s[t - d] : 0;
            __syncthreads();
            s[t] += add;
            __syncthreads();
        }
        int inc = s[t];
        int tot = s[1023];
        if (idx < N_NODES) {
            g_rowptr[idx + 1] = offset + inc;
            g_cursor[idx] = offset + inc - v;
        }
        offset += tot;
    }
    if (t == 0) g_rowptr[0] = 0;
}

__global__ void k_fill(const int* __restrict__ src, const int* __restrict__ dst) {
    int e = blockIdx.x * blockDim.x + threadIdx.x;
    if (e < N_EDGES) {
        int p = atomicAdd(&g_cursor[dst[e]], 1);
        g_csrc[p] = src[e];
    }
}

// ---------------- weight prep (transpose / pack) ----------------
// g_Wt[k*192 + part*64 + o] = mlpW[o*768 + part*256 + k]
__global__ void k_prep(const float* __restrict__ mlpW, const float* __restrict__ W1,
                       const float* __restrict__ W2, int layer) {
    int i = blockIdx.x * blockDim.x + threadIdx.x;
    if (i < 256 * 192) {
        int k = i / 192, j = i % 192;
        int part = j >> 6, o = j & 63;
        g_Wt[layer][i] = mlpW[o * 768 + part * 256 + k];
    }
    if (i < 4096) {
        int k = i >> 6, o = i & 63;
        g_W1T[layer][i] = W1[o * 64 + k];
        g_W2T[layer][i] = W2[o * 64 + k];
    }
}

// ---------------- aggregation: warp per node, CSR gather ----------------
__global__ __launch_bounds__(256) void k_aggr(const float* __restrict__ x) {
    int warp = (blockIdx.x * blockDim.x + threadIdx.x) >> 5;
    int lane = threadIdx.x & 31;
    if (warp >= N_NODES) return;

    int beg = g_rowptr[warp];
    int end = g_rowptr[warp + 1];

    float s0 = 0.f, s1 = 0.f, q0 = 0.f, q1 = 0.f;
    float m0 = -INFINITY, m1 = -INFINITY;

    int j = beg;
    for (; j + 32 <= end; j += 32) {
        int e = g_csrc[j + lane];
#pragma unroll
        for (int i = 0; i < 32; i++) {
            int sidx = __shfl_sync(0xffffffffu, e, i);
            float v0 = x[sidx * 64 + lane];
            float v1 = x[sidx * 64 + 32 + lane];
            s0 += v0; s1 += v1;
            q0 = fmaf(v0, v0, q0); q1 = fmaf(v1, v1, q1);
            m0 = fmaxf(m0, v0); m1 = fmaxf(m1, v1);
        }
    }
    int nrem = end - j;
    if (nrem > 0) {
        int e = (lane < nrem) ? g_csrc[j + lane] : 0;
        for (int i = 0; i < nrem; i++) {
            int sidx = __shfl_sync(0xffffffffu, e, i);
            float v0 = x[sidx * 64 + lane];
            float v1 = x[sidx * 64 + 32 + lane];
            s0 += v0; s1 += v1;
            q0 = fmaf(v0, v0, q0); q1 = fmaf(v1, v1, q1);
            m0 = fmaxf(m0, v0); m1 = fmaxf(m1, v1);
        }
    }

    float cnt = (float)(end - beg);
    float inv = 1.0f / cnt;
    float mean0 = s0 * inv, mean1 = s1 * inv;
    float var0 = fmaxf(q0 * inv - mean0 * mean0, 0.f);
    float var1 = fmaxf(q1 * inv - mean1 * mean1, 0.f);

    float* a = g_aggr + warp * 256;
    a[lane] = s0;        a[32 + lane] = s1;
    a[64 + lane] = m0;   a[96 + lane] = m1;
    a[128 + lane] = mean0; a[160 + lane] = mean1;
    a[192 + lane] = var0;  a[224 + lane] = var1;
}

// ---------------- fused MLP:  y=[N,256]x[256,192] -> combine -> W1 -> W2 -> relu + BN stats ----------------
__global__ __launch_bounds__(256) void k_mlp(const float* __restrict__ x,
                                             const float* __restrict__ mlpb,
                                             const float* __restrict__ b1v,
                                             const float* __restrict__ b2v,
                                             float* __restrict__ out, int layer) {
    __shared__ __align__(16) float smem[12288];       // 48KB
    float* sW  = smem;              // [32][192]   phase1
    float* sA  = smem + 6144;       // [32][64]    phase1
    float* sWT = smem;              // [64][64]    phase2/3 (W1T then W2T)
    float* sTT = smem + 4096;       // [64][64]    t transposed
    float* sHT = smem + 8192;       // [64][64]    h transposed
    float* scol = smem + 8192;      // [128] col stats (phase3 only; sHT dead)

    int t = threadIdx.x;
    int ng = t & 15, og = t >> 4;
    int nodeBase = blockIdx.x * 64;
    const float* Wt = g_Wt[layer];

    float acc[3][4][4];
#pragma unroll
    for (int p = 0; p < 3; p++)
#pragma unroll
        for (int i = 0; i < 4; i++)
#pragma unroll
            for (int jj = 0; jj < 4; jj++) acc[p][i][jj] = 0.f;

    for (int kc = 0; kc < 256; kc += 32) {
        for (int i = t; i < 1536; i += 256) {
            int kk = i / 48, f = i % 48;
            *(float4*)&sW[kk * 192 + f * 4] = *(const float4*)&Wt[(kc + kk) * 192 + f * 4];
        }
        for (int i = t; i < 512; i += 256) {
            int n = i >> 3, c = i & 7;
            int node = nodeBase + n;
            float4 v = make_float4(0.f, 0.f, 0.f, 0.f);
            if (node < N_NODES) v = *(const float4*)&g_aggr[node * 256 + kc + c * 4];
            sA[(c * 4 + 0) * 64 + n] = v.x;
            sA[(c * 4 + 1) * 64 + n] = v.y;
            sA[(c * 4 + 2) * 64 + n] = v.z;
            sA[(c * 4 + 3) * 64 + n] = v.w;
        }
        __syncthreads();
#pragma unroll 4
        for (int kk = 0; kk < 32; kk++) {
            float4 av = *(const float4*)&sA[kk * 64 + (ng << 2)];
            float a0 = av.x, a1 = av.y, a2 = av.z, a3 = av.w;
#pragma unroll
            for (int p = 0; p < 3; p++) {
                float4 bv = *(const float4*)&sW[kk * 192 + p * 64 + (og << 2)];
                acc[p][0][0] = fmaf(a0, bv.x, acc[p][0][0]);
                acc[p][0][1] = fmaf(a0, bv.y, acc[p][0][1]);
                acc[p][0][2] = fmaf(a0, bv.z, acc[p][0][2]);
                acc[p][0][3] = fmaf(a0, bv.w, acc[p][0][3]);
                acc[p][1][0] = fmaf(a1, bv.x, acc[p][1][0]);
                acc[p][1][1] = fmaf(a1, bv.y, acc[p][1][1]);
                acc[p][1][2] = fmaf(a1, bv.z, acc[p][1][2]);
                acc[p][1][3] = fmaf(a1, bv.w, acc[p][1][3]);
                acc[p][2][0] = fmaf(a2, bv.x, acc[p][2][0]);
                acc[p][2][1] = fmaf(a2, bv.y, acc[p][2][1]);
                acc[p][2][2] = fmaf(a2, bv.z, acc[p][2][2]);
                acc[p][2][3] = fmaf(a2, bv.w, acc[p][2][3]);
                acc[p][3][0] = fmaf(a3, bv.x, acc[p][3][0]);
                acc[p][3][1] = fmaf(a3, bv.y, acc[p][3][1]);
                acc[p][3][2] = fmaf(a3, bv.z, acc[p][3][2]);
                acc[p][3][3] = fmaf(a3, bv.w, acc[p][3][3]);
            }
        }
        __syncthreads();
    }

    // phase-1 epilogue: combine 3 parts with per-node scalars, add x, write h^T
    int nodes[4]; bool valid[4]; float s1v[4], s2v[4];
#pragma unroll
    for (int ni = 0; ni < 4; ni++) {
        int node = nodeBase + (ng << 2) + ni;
        nodes[ni] = node; valid[ni] = (node < N_NODES);
        float cnt = 1.f;
        if (valid[ni]) cnt = (float)(g_rowptr[node + 1] - g_rowptr[node]);
        s1v[ni] = cnt * (1.f / DELTA_C);
        s2v[ni] = DELTA_C / cnt;
    }
#pragma unroll
    for (int ni = 0; ni < 4; ni++) {
#pragma unroll
        for (int oi = 0; oi < 4; oi++) {
            int o = (og << 2) + oi;
            float a = acc[0][ni][oi] + s1v[ni] * acc[1][ni][oi] + s2v[ni] * acc[2][ni][oi] + mlpb[o];
            float h = a;
            if (valid[ni]) h += x[nodes[ni] * 64 + o];
            sHT[o * 64 + (ng << 2) + ni] = h;
        }
    }
    for (int i = t; i < 1024; i += 256)
        *(float4*)&sWT[i * 4] = *(const float4*)&g_W1T[layer][i * 4];
    __syncthreads();

    // phase 2: t = relu(W1 h + b1)
    float tacc[4][4];
#pragma unroll
    for (int i = 0; i < 4; i++)
#pragma unroll
        for (int jj = 0; jj < 4; jj++) tacc[i][jj] = 0.f;
#pragma unroll 4
    for (int k = 0; k < 64; k++) {
        float4 av = *(const float4*)&sHT[k * 64 + (ng << 2)];
        float4 bv = *(const float4*)&sWT[k * 64 + (og << 2)];
        float a[4] = {av.x, av.y, av.z, av.w};
        float b[4] = {bv.x, bv.y, bv.z, bv.w};
#pragma unroll
        for (int ni = 0; ni < 4; ni++)
#pragma unroll
            for (int oi = 0; oi < 4; oi++)
                tacc[ni][oi] = fmaf(a[ni], b[oi], tacc[ni][oi]);
    }
#pragma unroll
    for (int ni = 0; ni < 4; ni++)
#pragma unroll
        for (int oi = 0; oi < 4; oi++) {
            int o = (og << 2) + oi;
            sTT[o * 64 + (ng << 2) + ni] = fmaxf(tacc[ni][oi] + b1v[o], 0.f);
        }
    __syncthreads();

    for (int i = t; i < 1024; i += 256)
        *(float4*)&sWT[i * 4] = *(const float4*)&g_W2T[layer][i * 4];
    if (t < 128) scol[t] = 0.f;
    __syncthreads();

    // phase 3: out = relu(W2 t + b2), accumulate BN column stats
    float oacc[4][4];
#pragma unroll
    for (int i = 0; i < 4; i++)
#pragma unroll
        for (int jj = 0; jj < 4; jj++) oacc[i][jj] = 0.f;
#pragma unroll 4
    for (int k = 0; k < 64; k++) {
        float4 av = *(const float4*)&sTT[k * 64 + (ng << 2)];
        float4 bv = *(const float4*)&sWT[k * 64 + (og << 2)];
        float a[4] = {av.x, av.y, av.z, av.w};
        float b[4] = {bv.x, bv.y, bv.z, bv.w};
#pragma unroll
        for (int ni = 0; ni < 4; ni++)
#pragma unroll
            for (int oi = 0; oi < 4; oi++)
                oacc[ni][oi] = fmaf(a[ni], b[oi], oacc[ni][oi]);
    }
    float csum[4] = {0.f, 0.f, 0.f, 0.f};
    float csq[4]  = {0.f, 0.f, 0.f, 0.f};
#pragma unroll
    for (int ni = 0; ni < 4; ni++) {
        if (!valid[ni]) continue;
        float4 v;
        v.x = fmaxf(oacc[ni][0] + b2v[(og << 2) + 0], 0.f);
        v.y = fmaxf(oacc[ni][1] + b2v[(og << 2) + 1], 0.f);
        v.z = fmaxf(oacc[ni][2] + b2v[(og << 2) + 2], 0.f);
        v.w = fmaxf(oacc[ni][3] + b2v[(og << 2) + 3], 0.f);
        *(float4*)&out[nodes[ni] * 64 + (og << 2)] = v;
        csum[0] += v.x; csum[1] += v.y; csum[2] += v.z; csum[3] += v.w;
        csq[0] = fmaf(v.x, v.x, csq[0]); csq[1] = fmaf(v.y, v.y, csq[1]);
        csq[2] = fmaf(v.z, v.z, csq[2]); csq[3] = fmaf(v.w, v.w, csq[3]);
    }
#pragma unroll
    for (int oi = 0; oi < 4; oi++) {
        atomicAdd(&scol[(og << 2) + oi], csum[oi]);
        atomicAdd(&scol[64 + (og << 2) + oi], csq[oi]);
    }
    __syncthreads();
    if (t < 64) atomicAdd(&g_colsum[t], scol[t]);
    else if (t < 128) atomicAdd(&g_colsq[t - 64], scol[t]);
}

// ---------------- batchnorm apply ----------------
__global__ void k_bn(float* __restrict__ xf, const float* __restrict__ gg,
                     const float* __restrict__ bb) {
    int i = blockIdx.x * blockDim.x + threadIdx.x;
    if (i >= N_NODES * 64) return;
    int c = i & 63;
    float m = g_colsum[c] * (1.f / N_NODES);
    float v = g_colsq[c] * (1.f / N_NODES) - m * m;
    float scale = gg[c] / sqrtf(v + BN_EPS);
    xf[i] = (xf[i] - m) * scale + bb[c];
}

// ---------------- pooling (batch is sorted) ----------------
__global__ __launch_bounds__(256) void k_pool(const float* __restrict__ x,
                                              const int* __restrict__ batch) {
    __shared__ float ps[N_GRAPHS * 64];
    int t = threadIdx.x;
    for (int i = t; i < N_GRAPHS * 64; i += 256) ps[i] = 0.f;
    __syncthreads();

    const int CHUNK = (N_NODES + 127) / 128;   // 128 CTAs
    int start = blockIdx.x * CHUNK;
    int endn = min(start + CHUNK, N_NODES);

    int d = t & 63, r = t >> 6;
    float acc = 0.f; int curb = -1;
    for (int n = start + r; n < endn; n += 4) {
        int b = batch[n];
        if (b != curb) {
            if (curb >= 0) atomicAdd(&ps[curb * 64 + d], acc);
            curb = b; acc = 0.f;
        }
        acc += x[n * 64 + d];
    }
    if (curb >= 0) atomicAdd(&ps[curb * 64 + d], acc);
    __syncthreads();
    for (int i = t; i < N_GRAPHS * 64; i += 256)
        if (ps[i] != 0.f) atomicAdd(&g_pool[i], ps[i]);
}

// ---------------- head: fc1+relu -> fc2 -> log_softmax ----------------
__global__ __launch_bounds__(256) void k_head(const float* __restrict__ fc1W,
                                              const float* __restrict__ fc1b,
                                              const float* __restrict__ fc2W,
                                              const float* __restrict__ fc2b,
                                              float* __restrict__ out) {
    __shared__ float sT1[64 * 64];
    __shared__ float sT2[64 * 32];
    int t = threadIdx.x;
    for (int i = t; i < 4096; i += 256) {
        int gi = i >> 6, o = i & 63;
        float acc = fc1b[o];
        for (int k = 0; k < 64; k++) acc = fmaf(g_pool[gi * 64 + k], fc1W[o * 64 + k], acc);
        sT1[i] = fmaxf(acc, 0.f);
    }
    __syncthreads();
    for (int i = t; i < 2048; i += 256) {
        int gi = i >> 5, o = i & 31;
        float acc = fc2b[o];
        for (int k = 0; k < 64; k++) acc = fmaf(sT1[gi * 64 + k], fc2W[o * 64 + k], acc);
        sT2[i] = acc;
    }
    __syncthreads();
    int w = t >> 5, lane = t & 31;
    for (int gi = w; gi < 64; gi += 8) {
        float v = sT2[gi * 32 + lane];
        float mx = v;
        for (int o = 16; o > 0; o >>= 1) mx = fmaxf(mx, __shfl_xor_sync(0xffffffffu, mx, o));
        float e = expf(v - mx);
        float s = e;
        for (int o = 16; o > 0; o >>= 1) s += __shfl_xor_sync(0xffffffffu, s, o);
        out[gi * 32 + lane] = v - mx - logf(s);
    }
}

// ---------------- launch ----------------
// metadata.txt / setup_inputs() dict order:
//   0:x 1:edge_index 2:batch
//   3..8:   c1 (mlp_W, mlp_b, W1, b1, W2, b2)
//   9..14:  c2
//   15..20: c3
//   21..26: bn1_g, bn1_b, bn2_g, bn2_b, bn3_g, bn3_b
//   27..30: fc1_W, fc1_b, fc2_W, fc2_b
extern "C" void kernel_launch(void* const* d_in, const int* in_sizes, int n_in,
                              void* d_out, int out_size) {
    const float* x = (const float*)d_in[0];
    const int* ei = (const int*)d_in[1];
    const int* src = ei;
    const int* dst = ei + N_EDGES;
    const int* batch = (const int*)d_in[2];
    float* out = (float*)d_out;

    float *featA = nullptr, *featB = nullptr;
    cudaGetSymbolAddress((void**)&featA, g_featA);
    cudaGetSymbolAddress((void**)&featB, g_featB);

    // CSR build (edges identical every call; rebuilt each launch for determinism rules)
    k_zero_deg<<<(N_NODES + 255) / 256, 256>>>();
    k_count<<<(N_EDGES + 255) / 256, 256>>>(dst);
    k_scan<<<1, 1024>>>();
    k_fill<<<(N_EDGES + 255) / 256, 256>>>(src, dst);

    for (int L = 0; L < 3; L++)
        k_prep<<<192, 256>>>((const float*)d_in[3 + 6 * L],
                             (const float*)d_in[5 + 6 * L],
                             (const float*)d_in[7 + 6 * L], L);

    const float* cur = x;
    float* nxt = featA;
    for (int L = 0; L < 3; L++) {
        k_aggr<<<(N_NODES * 32 + 255) / 256, 256>>>(cur);
        k_zero_stats<<<1, 64>>>();
        k_mlp<<<(N_NODES + 63) / 64, 256>>>(cur,
                                            (const float*)d_in[4 + 6 * L],
                                            (const float*)d_in[6 + 6 * L],
                                            (const float*)d_in[8 + 6 * L],
                                            nxt, L);
        k_bn<<<(N_NODES * 64 + 255) / 256, 256>>>(nxt,
                                                  (const float*)d_in[21 + 2 * L],
                                                  (const float*)d_in[22 + 2 * L]);
        cur = nxt;
        nxt = (nxt == featA) ? featB : featA;
    }

    k_zero_pool<<<16, 256>>>();
    k_pool<<<128, 256>>>(cur, batch);
    k_head<<<1, 256>>>((const float*)d_in[27], (const float*)d_in[28],
                       (const float*)d_in[29], (const float*)d_in[30], out);
}

// round 3
// speedup vs baseline: 1.1619x; 1.1619x over previous
#include <cuda_runtime.h>
#include <math.h>

#define N_NODES 50000
#define N_EDGES 1600000
#define N_GRAPHS 64
#define DELTA_C 2.5749f
#define BN_EPS 1e-5f
#define NB_SCAN 49   // ceil(50000/1024)

// ---------------- scratch ----------------
__device__ float g_featA[N_NODES * 64];
__device__ float g_featB[N_NODES * 64];
__device__ float g_aggr[N_NODES * 256];
__device__ int   g_deg[N_NODES];
__device__ int   g_rowptr[N_NODES + 1];
__device__ int   g_cursor[N_NODES];
__device__ int   g_csrc[N_EDGES];
__device__ int   g_blksum[64];
__device__ int   g_blkoff[64];
__device__ float g_Wt[3][256 * 192];
__device__ float g_W1T[3][64 * 64];
__device__ float g_W2T[3][64 * 64];
__device__ float g_colsum[64];
__device__ float g_colsq[64];
__device__ float g_pool[N_GRAPHS * 64];

// ---------------- f32x2 helpers ----------------
__device__ __forceinline__ unsigned long long pk2(float x) {
    unsigned long long r;
    asm("mov.b64 %0, {%1,%1};" : "=l"(r) : "f"(x));
    return r;
}
__device__ __forceinline__ unsigned long long fma2(unsigned long long a,
                                                   unsigned long long b,
                                                   unsigned long long c) {
    unsigned long long d;
    asm("fma.rn.f32x2 %0, %1, %2, %3;" : "=l"(d) : "l"(a), "l"(b), "l"(c));
    return d;
}
__device__ __forceinline__ float2 up2(unsigned long long v) {
    float2 f;
    asm("mov.b64 {%0,%1}, %2;" : "=f"(f.x), "=f"(f.y) : "l"(v));
    return f;
}

// ---------------- CSR build ----------------
__global__ void k_zero_deg() {
    int i = blockIdx.x * blockDim.x + threadIdx.x;
    if (i < N_NODES) g_deg[i] = 0;
}
__global__ void k_count(const int* __restrict__ dst) {
    int e = blockIdx.x * blockDim.x + threadIdx.x;
    if (e < N_EDGES) atomicAdd(&g_deg[dst[e]], 1);
}
__global__ void k_scan_blk() {
    __shared__ int s[1024];
    int t = threadIdx.x;
    int idx = blockIdx.x * 1024 + t;
    int v = (idx < N_NODES) ? g_deg[idx] : 0;
    s[t] = v;
    __syncthreads();
    for (int d = 1; d < 1024; d <<= 1) {
        int add = (t >= d) ? s[t - d] : 0;
        __syncthreads();
        s[t] += add;
        __syncthreads();
    }
    if (idx < N_NODES) g_rowptr[idx + 1] = s[t];
    if (t == 1023) g_blksum[blockIdx.x] = s[1023];
}
__global__ void k_scan_top() {
    __shared__ int s[64];
    int t = threadIdx.x;
    int v = (t < NB_SCAN) ? g_blksum[t] : 0;
    s[t] = v;
    __syncthreads();
    for (int d = 1; d < 64; d <<= 1) {
        int add = (t >= d) ? s[t - d] : 0;
        __syncthreads();
        s[t] += add;
        __syncthreads();
    }
    g_blkoff[t] = s[t] - v;   // exclusive
}
__global__ void k_scan_add() {
    int idx = blockIdx.x * blockDim.x + threadIdx.x;
    if (idx < N_NODES) {
        int r = g_rowptr[idx + 1] + g_blkoff[idx >> 10];
        g_rowptr[idx + 1] = r;
        g_cursor[idx] = r - g_deg[idx];
    }
    if (idx == 0) g_rowptr[0] = 0;
    if (idx < N_GRAPHS * 64) g_pool[idx] = 0.f;
}
__global__ void k_fill(const int* __restrict__ src, const int* __restrict__ dst) {
    int e = blockIdx.x * blockDim.x + threadIdx.x;
    if (e < N_EDGES) {
        int p = atomicAdd(&g_cursor[dst[e]], 1);
        g_csrc[p] = src[e];
    }
}

// ---------------- weight prep ----------------
__global__ void k_prep(const float* __restrict__ mlpW, const float* __restrict__ W1,
                       const float* __restrict__ W2, int layer) {
    int i = blockIdx.x * blockDim.x + threadIdx.x;
    if (i < 256 * 192) {
        int k = i / 192, j = i % 192;
        int part = j >> 6, o = j & 63;
        g_Wt[layer][i] = mlpW[o * 768 + part * 256 + k];
    }
    if (i < 4096) {
        int k = i >> 6, o = i & 63;
        g_W1T[layer][i] = W1[o * 64 + k];
        g_W2T[layer][i] = W2[o * 64 + k];
    }
}

// ---------------- aggregation: warp per node, CSR gather ----------------
__global__ __launch_bounds__(256) void k_aggr(const float* __restrict__ x) {
    if (blockIdx.x == 0 && threadIdx.x < 64) {      // zero BN stats for this layer
        g_colsum[threadIdx.x] = 0.f;
        g_colsq[threadIdx.x] = 0.f;
    }
    int warp = (blockIdx.x * blockDim.x + threadIdx.x) >> 5;
    int lane = threadIdx.x & 31;
    if (warp >= N_NODES) return;

    int beg = g_rowptr[warp];
    int end = g_rowptr[warp + 1];

    float s0 = 0.f, s1 = 0.f, q0 = 0.f, q1 = 0.f;
    float m0 = -INFINITY, m1 = -INFINITY;

    int j = beg;
    for (; j + 32 <= end; j += 32) {
        int e = g_csrc[j + lane];
#pragma unroll
        for (int i = 0; i < 32; i++) {
            int sidx = __shfl_sync(0xffffffffu, e, i);
            float2 v = *(const float2*)&x[sidx * 64 + 2 * lane];
            s0 += v.x; s1 += v.y;
            q0 = fmaf(v.x, v.x, q0); q1 = fmaf(v.y, v.y, q1);
            m0 = fmaxf(m0, v.x); m1 = fmaxf(m1, v.y);
        }
    }
    int nrem = end - j;
    if (nrem > 0) {
        int e = (lane < nrem) ? g_csrc[j + lane] : 0;
        for (int i = 0; i < nrem; i++) {
            int sidx = __shfl_sync(0xffffffffu, e, i);
            float2 v = *(const float2*)&x[sidx * 64 + 2 * lane];
            s0 += v.x; s1 += v.y;
            q0 = fmaf(v.x, v.x, q0); q1 = fmaf(v.y, v.y, q1);
            m0 = fmaxf(m0, v.x); m1 = fmaxf(m1, v.y);
        }
    }

    float cnt = (float)(end - beg);
    float inv = 1.0f / cnt;
    float mean0 = s0 * inv, mean1 = s1 * inv;
    float var0 = fmaxf(q0 * inv - mean0 * mean0, 0.f);
    float var1 = fmaxf(q1 * inv - mean1 * mean1, 0.f);

    float* a = g_aggr + warp * 256;
    *(float2*)&a[2 * lane]       = make_float2(s0, s1);
    *(float2*)&a[64 + 2 * lane]  = make_float2(m0, m1);
    *(float2*)&a[128 + 2 * lane] = make_float2(mean0, mean1);
    *(float2*)&a[192 + 2 * lane] = make_float2(var0, var1);
}

// ---------------- fused MLP (f32x2 packed math) ----------------
__global__ __launch_bounds__(256) void k_mlp(const float* __restrict__ x,
                                             const float* __restrict__ mlpb,
                                             const float* __restrict__ b1v,
                                             const float* __restrict__ b2v,
                                             float* __restrict__ out, int layer) {
    __shared__ __align__(16) float smem[12288];
    float* sW  = smem;              // [32][192]
    float* sA  = smem + 6144;       // [32][64]
    float* sWT = smem;              // [64][64]
    float* sTT = smem + 4096;       // [64][64]
    float* sHT = smem + 8192;       // [64][64]
    float* scol = smem + 8192;      // [128]

    int t = threadIdx.x;
    int ng = t & 15, og = t >> 4;
    int nodeBase = blockIdx.x * 64;
    const float* Wt = g_Wt[layer];

    unsigned long long acc[3][4][2];
#pragma unroll
    for (int p = 0; p < 3; p++)
#pragma unroll
        for (int i = 0; i < 4; i++) { acc[p][i][0] = 0ULL; acc[p][i][1] = 0ULL; }

    for (int kc = 0; kc < 256; kc += 32) {
        for (int i = t; i < 1536; i += 256) {
            int kk = i / 48, f = i % 48;
            *(float4*)&sW[kk * 192 + f * 4] = *(const float4*)&Wt[(kc + kk) * 192 + f * 4];
        }
        for (int i = t; i < 512; i += 256) {
            int n = i >> 3, c = i & 7;
            int node = nodeBase + n;
            float4 v = make_float4(0.f, 0.f, 0.f, 0.f);
            if (node < N_NODES) v = *(const float4*)&g_aggr[node * 256 + kc + c * 4];
            sA[(c * 4 + 0) * 64 + n] = v.x;
            sA[(c * 4 + 1) * 64 + n] = v.y;
            sA[(c * 4 + 2) * 64 + n] = v.z;
            sA[(c * 4 + 3) * 64 + n] = v.w;
        }
        __syncthreads();
#pragma unroll 4
        for (int kk = 0; kk < 32; kk++) {
            float4 av = *(const float4*)&sA[kk * 64 + (ng << 2)];
            unsigned long long ap[4] = {pk2(av.x), pk2(av.y), pk2(av.z), pk2(av.w)};
#pragma unroll
            for (int p = 0; p < 3; p++) {
                ulonglong2 bq = *(const ulonglong2*)&sW[kk * 192 + p * 64 + (og << 2)];
#pragma unroll
                for (int ni = 0; ni < 4; ni++) {
                    acc[p][ni][0] = fma2(ap[ni], bq.x, acc[p][ni][0]);
                    acc[p][ni][1] = fma2(ap[ni], bq.y, acc[p][ni][1]);
                }
            }
        }
        __syncthreads();
    }

    // epilogue 1: combine parts with per-node scalars, add x, write h^T
    int nodes[4]; bool valid[4]; float s1v[4], s2v[4];
#pragma unroll
    for (int ni = 0; ni < 4; ni++) {
        int node = nodeBase + (ng << 2) + ni;
        nodes[ni] = node; valid[ni] = (node < N_NODES);
        float cnt = 1.f;
        if (valid[ni]) cnt = (float)(g_rowptr[node + 1] - g_rowptr[node]);
        s1v[ni] = cnt * (1.f / DELTA_C);
        s2v[ni] = DELTA_C / cnt;
    }
#pragma unroll
    for (int ni = 0; ni < 4; ni++) {
#pragma unroll
        for (int j = 0; j < 2; j++) {
            float2 a0 = up2(acc[0][ni][j]);
            float2 a1 = up2(acc[1][ni][j]);
            float2 a2 = up2(acc[2][ni][j]);
            int o = (og << 2) + 2 * j;
            float hx = a0.x + s1v[ni] * a1.x + s2v[ni] * a2.x + mlpb[o];
            float hy = a0.y + s1v[ni] * a1.y + s2v[ni] * a2.y + mlpb[o + 1];
            if (valid[ni]) {
                hx += x[nodes[ni] * 64 + o];
                hy += x[nodes[ni] * 64 + o + 1];
            }
            sHT[o * 64 + (ng << 2) + ni] = hx;
            sHT[(o + 1) * 64 + (ng << 2) + ni] = hy;
        }
    }
    for (int i = t; i < 1024; i += 256)
        *(float4*)&sWT[i * 4] = *(const float4*)&g_W1T[layer][i * 4];
    __syncthreads();

    // phase 2: t = relu(W1 h + b1)
    unsigned long long tacc[4][2];
#pragma unroll
    for (int i = 0; i < 4; i++) { tacc[i][0] = 0ULL; tacc[i][1] = 0ULL; }
#pragma unroll 4
    for (int k = 0; k < 64; k++) {
        float4 av = *(const float4*)&sHT[k * 64 + (ng << 2)];
        unsigned long long ap[4] = {pk2(av.x), pk2(av.y), pk2(av.z), pk2(av.w)};
        ulonglong2 bq = *(const ulonglong2*)&sWT[k * 64 + (og << 2)];
#pragma unroll
        for (int ni = 0; ni < 4; ni++) {
            tacc[ni][0] = fma2(ap[ni], bq.x, tacc[ni][0]);
            tacc[ni][1] = fma2(ap[ni], bq.y, tacc[ni][1]);
        }
    }
#pragma unroll
    for (int ni = 0; ni < 4; ni++)
#pragma unroll
        for (int j = 0; j < 2; j++) {
            float2 v = up2(tacc[ni][j]);
            int o = (og << 2) + 2 * j;
            sTT[o * 64 + (ng << 2) + ni] = fmaxf(v.x + b1v[o], 0.f);
            sTT[(o + 1) * 64 + (ng << 2) + ni] = fmaxf(v.y + b1v[o + 1], 0.f);
        }
    __syncthreads();

    for (int i = t; i < 1024; i += 256)
        *(float4*)&sWT[i * 4] = *(const float4*)&g_W2T[layer][i * 4];
    if (t < 128) scol[t] = 0.f;
    __syncthreads();

    // phase 3: out = relu(W2 t + b2) + BN stats
    unsigned long long oacc[4][2];
#pragma unroll
    for (int i = 0; i < 4; i++) { oacc[i][0] = 0ULL; oacc[i][1] = 0ULL; }
#pragma unroll 4
    for (int k = 0; k < 64; k++) {
        float4 av = *(const float4*)&sTT[k * 64 + (ng << 2)];
        unsigned long long ap[4] = {pk2(av.x), pk2(av.y), pk2(av.z), pk2(av.w)};
        ulonglong2 bq = *(const ulonglong2*)&sWT[k * 64 + (og << 2)];
#pragma unroll
        for (int ni = 0; ni < 4; ni++) {
            oacc[ni][0] = fma2(ap[ni], bq.x, oacc[ni][0]);
            oacc[ni][1] = fma2(ap[ni], bq.y, oacc[ni][1]);
        }
    }
    float csum[4] = {0.f, 0.f, 0.f, 0.f};
    float csq[4]  = {0.f, 0.f, 0.f, 0.f};
#pragma unroll
    for (int ni = 0; ni < 4; ni++) {
        if (!valid[ni]) continue;
        float2 p0 = up2(oacc[ni][0]);
        float2 p1 = up2(oacc[ni][1]);
        float4 v;
        v.x = fmaxf(p0.x + b2v[(og << 2) + 0], 0.f);
        v.y = fmaxf(p0.y + b2v[(og << 2) + 1], 0.f);
        v.z = fmaxf(p1.x + b2v[(og << 2) + 2], 0.f);
        v.w = fmaxf(p1.y + b2v[(og << 2) + 3], 0.f);
        *(float4*)&out[nodes[ni] * 64 + (og << 2)] = v;
        csum[0] += v.x; csum[1] += v.y; csum[2] += v.z; csum[3] += v.w;
        csq[0] = fmaf(v.x, v.x, csq[0]); csq[1] = fmaf(v.y, v.y, csq[1]);
        csq[2] = fmaf(v.z, v.z, csq[2]); csq[3] = fmaf(v.w, v.w, csq[3]);
    }
#pragma unroll
    for (int oi = 0; oi < 4; oi++) {
        atomicAdd(&scol[(og << 2) + oi], csum[oi]);
        atomicAdd(&scol[64 + (og << 2) + oi], csq[oi]);
    }
    __syncthreads();
    if (t < 64) atomicAdd(&g_colsum[t], scol[t]);
    else if (t < 128) atomicAdd(&g_colsq[t - 64], scol[t]);
}

// ---------------- batchnorm apply (float4) ----------------
__global__ void k_bn(float* __restrict__ xf, const float* __restrict__ gg,
                     const float* __restrict__ bb) {
    int i = blockIdx.x * blockDim.x + threadIdx.x;
    if (i >= N_NODES * 16) return;
    int c = (i & 15) << 2;
    float4 v = *(float4*)&xf[i * 4];
    float m0 = g_colsum[c] * (1.f / N_NODES), m1 = g_colsum[c + 1] * (1.f / N_NODES);
    float m2 = g_colsum[c + 2] * (1.f / N_NODES), m3 = g_colsum[c + 3] * (1.f / N_NODES);
    float s0 = gg[c] * rsqrtf(g_colsq[c] * (1.f / N_NODES) - m0 * m0 + BN_EPS);
    float s1 = gg[c + 1] * rsqrtf(g_colsq[c + 1] * (1.f / N_NODES) - m1 * m1 + BN_EPS);
    float s2 = gg[c + 2] * rsqrtf(g_colsq[c + 2] * (1.f / N_NODES) - m2 * m2 + BN_EPS);
    float s3 = gg[c + 3] * rsqrtf(g_colsq[c + 3] * (1.f / N_NODES) - m3 * m3 + BN_EPS);
    v.x = (v.x - m0) * s0 + bb[c];
    v.y = (v.y - m1) * s1 + bb[c + 1];
    v.z = (v.z - m2) * s2 + bb[c + 2];
    v.w = (v.w - m3) * s3 + bb[c + 3];
    *(float4*)&xf[i * 4] = v;
}

// ---------------- pooling ----------------
__global__ __launch_bounds__(256) void k_pool(const float* __restrict__ x,
                                              const int* __restrict__ batch) {
    __shared__ float ps[N_GRAPHS * 64];
    int t = threadIdx.x;
    for (int i = t; i < N_GRAPHS * 64; i += 256) ps[i] = 0.f;
    __syncthreads();

    const int CHUNK = (N_NODES + 127) / 128;
    int start = blockIdx.x * CHUNK;
    int endn = min(start + CHUNK, N_NODES);

    int d = t & 63, r = t >> 6;
    float acc = 0.f; int curb = -1;
    for (int n = start + r; n < endn; n += 4) {
        int b = batch[n];
        if (b != curb) {
            if (curb >= 0) atomicAdd(&ps[curb * 64 + d], acc);
            curb = b; acc = 0.f;
        }
        acc += x[n * 64 + d];
    }
    if (curb >= 0) atomicAdd(&ps[curb * 64 + d], acc);
    __syncthreads();
    for (int i = t; i < N_GRAPHS * 64; i += 256)
        if (ps[i] != 0.f) atomicAdd(&g_pool[i], ps[i]);
}

// ---------------- head ----------------
__global__ __launch_bounds__(256) void k_head(const float* __restrict__ fc1W,
                                              const float* __restrict__ fc1b,
                                              const float* __restrict__ fc2W,
                                              const float* __restrict__ fc2b,
                                              float* __restrict__ out) {
    __shared__ float sT1[64 * 64];
    __shared__ float sT2[64 * 32];
    int t = threadIdx.x;
    for (int i = t; i < 4096; i += 256) {
        int gi = i >> 6, o = i & 63;
        float acc = fc1b[o];
        for (int k = 0; k < 64; k++) acc = fmaf(g_pool[gi * 64 + k], fc1W[o * 64 + k], acc);
        sT1[i] = fmaxf(acc, 0.f);
    }
    __syncthreads();
    for (int i = t; i < 2048; i += 256) {
        int gi = i >> 5, o = i & 31;
        float acc = fc2b[o];
        for (int k = 0; k < 64; k++) acc = fmaf(sT1[gi * 64 + k], fc2W[o * 64 + k], acc);
        sT2[i] = acc;
    }
    __syncthreads();
    int w = t >> 5, lane = t & 31;
    for (int gi = w; gi < 64; gi += 8) {
        float v = sT2[gi * 32 + lane];
        float mx = v;
        for (int o = 16; o > 0; o >>= 1) mx = fmaxf(mx, __shfl_xor_sync(0xffffffffu, mx, o));
        float e = expf(v - mx);
        float s = e;
        for (int o = 16; o > 0; o >>= 1) s += __shfl_xor_sync(0xffffffffu, s, o);
        out[gi * 32 + lane] = v - mx - logf(s);
    }
}

// ---------------- launch ----------------
// input order: 0:x 1:edge_index 2:batch | 3..8 c1 | 9..14 c2 | 15..20 c3 |
//              21..26 bn1_g,bn1_b,bn2_g,bn2_b,bn3_g,bn3_b | 27..30 fc
extern "C" void kernel_launch(void* const* d_in, const int* in_sizes, int n_in,
                              void* d_out, int out_size) {
    const float* x = (const float*)d_in[0];
    const int* ei = (const int*)d_in[1];
    const int* src = ei;
    const int* dst = ei + N_EDGES;
    const int* batch = (const int*)d_in[2];
    float* out = (float*)d_out;

    float *featA = nullptr, *featB = nullptr;
    cudaGetSymbolAddress((void**)&featA, g_featA);
    cudaGetSymbolAddress((void**)&featB, g_featB);

    k_zero_deg<<<(N_NODES + 255) / 256, 256>>>();
    k_count<<<(N_EDGES + 255) / 256, 256>>>(dst);
    k_scan_blk<<<NB_SCAN, 1024>>>();
    k_scan_top<<<1, 64>>>();
    k_scan_add<<<(N_NODES + 256) / 256, 256>>>();
    k_fill<<<(N_EDGES + 255) / 256, 256>>>(src, dst);

    for (int L = 0; L < 3; L++)
        k_prep<<<192, 256>>>((const float*)d_in[3 + 6 * L],
                             (const float*)d_in[5 + 6 * L],
                             (const float*)d_in[7 + 6 * L], L);

    const float* cur = x;
    float* nxt = featA;
    for (int L = 0; L < 3; L++) {
        k_aggr<<<(N_NODES * 32 + 255) / 256, 256>>>(cur);
        k_mlp<<<(N_NODES + 63) / 64, 256>>>(cur,
                                            (const float*)d_in[4 + 6 * L],
                                            (const float*)d_in[6 + 6 * L],
                                            (const float*)d_in[8 + 6 * L],
                                            nxt, L);
        k_bn<<<(N_NODES * 16 + 255) / 256, 256>>>(nxt,
                                                  (const float*)d_in[21 + 2 * L],
                                                  (const float*)d_in[22 + 2 * L]);
        cur = nxt;
        nxt = (nxt == featA) ? featB : featA;
    }

    k_pool<<<128, 256>>>(cur, batch);
    k_head<<<1, 256>>>((const float*)d_in[27], (const float*)d_in[28],
                       (const float*)d_in[29], (const float*)d_in[30], out);
}

// round 5
// speedup vs baseline: 1.4071x; 1.2110x over previous
#include <cuda_runtime.h>
#include <cuda_bf16.h>
#include <math.h>
#include <stdint.h>

#define N_NODES 50000
#define N_EDGES 1600000
#define N_GRAPHS 64
#define DELTA_C 2.5749f
#define BN_EPS 1e-5f
#define NB_SCAN 49

// ---------------- scratch ----------------
__device__ float g_featA[N_NODES * 64];
__device__ float g_featB[N_NODES * 64];
__device__ float g_aggr[N_NODES * 256];
__device__ int   g_deg[N_NODES];
__device__ int   g_rowptr[N_NODES + 1];
__device__ int   g_cursor[N_NODES];
__device__ int   g_csrc[N_EDGES];
__device__ int   g_blksum[64];
__device__ int   g_blkoff[64];
__device__ __nv_bfloat16 g_Whi[3][192 * 256];   // [p*64+o][k]
__device__ __nv_bfloat16 g_Wlo[3][192 * 256];
__device__ float g_W1T[3][64 * 64];
__device__ float g_W2T[3][64 * 64];
__device__ float g_colsum[64];
__device__ float g_colsq[64];
__device__ float g_pool[N_GRAPHS * 64];

// smem layout for k_mlp (dynamic):
#define SA_STRIDE 264              // elements, conflict-free for frag loads
#define SW_STRIDE 72
#define AHI_OFF 0                  // 128*264*2 = 67584
#define ALO_OFF 67584              // ends 135168
#define WHI_OFF 135168             // 192*72*2 = 27648 -> 162816
#define WLO_OFF 162816             // ends 190464
#define MLP_SMEM 190464
// phase-2/3 overlay (inside dead A region):
#define HT_OFF 0                   // [64][128] f32, 32KB
#define TT_OFF 32768               // [64][128] f32, 32KB
#define WT_OFF 65536               // [64][64] f32, 16KB
#define SCOL_OFF 81920             // [128] f32

// ---------------- f32x2 helpers ----------------
__device__ __forceinline__ unsigned long long pk2(float x) {
    unsigned long long r;
    asm("mov.b64 %0, {%1,%1};" : "=l"(r) : "f"(x));
    return r;
}
__device__ __forceinline__ unsigned long long fma2(unsigned long long a,
                                                   unsigned long long b,
                                                   unsigned long long c) {
    unsigned long long d;
    asm("fma.rn.f32x2 %0, %1, %2, %3;" : "=l"(d) : "l"(a), "l"(b), "l"(c));
    return d;
}
__device__ __forceinline__ float2 up2(unsigned long long v) {
    float2 f;
    asm("mov.b64 {%0,%1}, %2;" : "=f"(f.x), "=f"(f.y) : "l"(v));
    return f;
}

// ---------------- warp mma ----------------
__device__ __forceinline__ void mma_bf16(float* acc, uint32_t a0, uint32_t a1,
                                         uint32_t a2, uint32_t a3,
                                         uint32_t b0, uint32_t b1) {
    asm volatile("mma.sync.aligned.m16n8k16.row.col.f32.bf16.bf16.f32 "
        "{%0,%1,%2,%3}, {%4,%5,%6,%7}, {%8,%9}, {%0,%1,%2,%3};"
        : "+f"(acc[0]), "+f"(acc[1]), "+f"(acc[2]), "+f"(acc[3])
        : "r"(a0), "r"(a1), "r"(a2), "r"(a3), "r"(b0), "r"(b1));
}

// ---------------- CSR build ----------------
__global__ void k_zero_deg() {
    int i = blockIdx.x * blockDim.x + threadIdx.x;
    if (i < N_NODES) g_deg[i] = 0;
}
__global__ void k_count(const int* __restrict__ dst) {
    int e = blockIdx.x * blockDim.x + threadIdx.x;
    if (e < N_EDGES) atomicAdd(&g_deg[dst[e]], 1);
}
__global__ void k_scan_blk() {
    __shared__ int s[1024];
    int t = threadIdx.x;
    int idx = blockIdx.x * 1024 + t;
    int v = (idx < N_NODES) ? g_deg[idx] : 0;
    s[t] = v;
    __syncthreads();
    for (int d = 1; d < 1024; d <<= 1) {
        int add = (t >= d) ? s[t - d] : 0;
        __syncthreads();
        s[t] += add;
        __syncthreads();
    }
    if (idx < N_NODES) g_rowptr[idx + 1] = s[t];
    if (t == 1023) g_blksum[blockIdx.x] = s[1023];
}
__global__ void k_scan_top() {
    __shared__ int s[64];
    int t = threadIdx.x;
    int v = (t < NB_SCAN) ? g_blksum[t] : 0;
    s[t] = v;
    __syncthreads();
    for (int d = 1; d < 64; d <<= 1) {
        int add = (t >= d) ? s[t - d] : 0;
        __syncthreads();
        s[t] += add;
        __syncthreads();
    }
    g_blkoff[t] = s[t] - v;
}
__global__ void k_scan_add() {
    int idx = blockIdx.x * blockDim.x + threadIdx.x;
    if (idx < N_NODES) {
        int r = g_rowptr[idx + 1] + g_blkoff[idx >> 10];
        g_rowptr[idx + 1] = r;
        g_cursor[idx] = r - g_deg[idx];
    }
    if (idx == 0) g_rowptr[0] = 0;
    if (idx < N_GRAPHS * 64) g_pool[idx] = 0.f;
}
__global__ void k_fill(const int* __restrict__ src, const int* __restrict__ dst) {
    int e = blockIdx.x * blockDim.x + threadIdx.x;
    if (e < N_EDGES) {
        int p = atomicAdd(&g_cursor[dst[e]], 1);
        g_csrc[p] = src[e];
    }
}

// ---------------- weight prep ----------------
__global__ void k_prep(const float* __restrict__ mlpW, const float* __restrict__ W1,
                       const float* __restrict__ W2, int layer) {
    int i = blockIdx.x * blockDim.x + threadIdx.x;
    if (i < 192 * 256) {
        int j = i >> 8, k = i & 255;
        int p = j >> 6, o = j & 63;
        float w = mlpW[o * 768 + p * 256 + k];
        __nv_bfloat16 hi = __float2bfloat16(w);
        __nv_bfloat16 lo = __float2bfloat16(w - __bfloat162float(hi));
        g_Whi[layer][i] = hi;
        g_Wlo[layer][i] = lo;
    }
    if (i < 4096) {
        int k = i >> 6, o = i & 63;
        g_W1T[layer][i] = W1[o * 64 + k];
        g_W2T[layer][i] = W2[o * 64 + k];
    }
}

// ---------------- aggregation ----------------
__global__ __launch_bounds__(256) void k_aggr(const float* __restrict__ x) {
    if (blockIdx.x == 0 && threadIdx.x < 64) {
        g_colsum[threadIdx.x] = 0.f;
        g_colsq[threadIdx.x] = 0.f;
    }
    int warp = (blockIdx.x * blockDim.x + threadIdx.x) >> 5;
    int lane = threadIdx.x & 31;
    if (warp >= N_NODES) return;

    int beg = g_rowptr[warp];
    int end = g_rowptr[warp + 1];

    float s0 = 0.f, s1 = 0.f, q0 = 0.f, q1 = 0.f;
    float m0 = -INFINITY, m1 = -INFINITY;

    int j = beg;
    for (; j + 32 <= end; j += 32) {
        int e = g_csrc[j + lane];
#pragma unroll
        for (int i = 0; i < 32; i++) {
            int sidx = __shfl_sync(0xffffffffu, e, i);
            float2 v = *(const float2*)&x[sidx * 64 + 2 * lane];
            s0 += v.x; s1 += v.y;
            q0 = fmaf(v.x, v.x, q0); q1 = fmaf(v.y, v.y, q1);
            m0 = fmaxf(m0, v.x); m1 = fmaxf(m1, v.y);
        }
    }
    int nrem = end - j;
    if (nrem > 0) {
        int e = (lane < nrem) ? g_csrc[j + lane] : 0;
        for (int i = 0; i < nrem; i++) {
            int sidx = __shfl_sync(0xffffffffu, e, i);
            float2 v = *(const float2*)&x[sidx * 64 + 2 * lane];
            s0 += v.x; s1 += v.y;
            q0 = fmaf(v.x, v.x, q0); q1 = fmaf(v.y, v.y, q1);
            m0 = fmaxf(m0, v.x); m1 = fmaxf(m1, v.y);
        }
    }

    float cnt = (float)(end - beg);
    float inv = 1.0f / cnt;
    float mean0 = s0 * inv, mean1 = s1 * inv;
    float var0 = fmaxf(q0 * inv - mean0 * mean0, 0.f);
    float var1 = fmaxf(q1 * inv - mean1 * mean1, 0.f);

    float* a = g_aggr + warp * 256;
    *(float2*)&a[2 * lane]       = make_float2(s0, s1);
    *(float2*)&a[64 + 2 * lane]  = make_float2(m0, m1);
    *(float2*)&a[128 + 2 * lane] = make_float2(mean0, mean1);
    *(float2*)&a[192 + 2 * lane] = make_float2(var0, var1);
}

// ---------------- fused MLP: mma.sync phase1 + f32x2 phases 2/3 ----------------
// D[128x192] = A[128x256] @ W[192x256]^T, 2-term bf16 split, fp32 accum.
__global__ __launch_bounds__(256) void k_mlp(const float* __restrict__ x,
                                             const float* __restrict__ mlpb,
                                             const float* __restrict__ b1v,
                                             const float* __restrict__ b2v,
                                             float* __restrict__ out, int layer) {
    extern __shared__ __align__(16) char smem[];
    __nv_bfloat16* sAhi = (__nv_bfloat16*)(smem + AHI_OFF);
    __nv_bfloat16* sAlo = (__nv_bfloat16*)(smem + ALO_OFF);
    __nv_bfloat16* sWhi = (__nv_bfloat16*)(smem + WHI_OFF);
    __nv_bfloat16* sWlo = (__nv_bfloat16*)(smem + WLO_OFF);
    float* sHT  = (float*)(smem + HT_OFF);
    float* sTT  = (float*)(smem + TT_OFF);
    float* sWT  = (float*)(smem + WT_OFF);
    float* scol = (float*)(smem + SCOL_OFF);

    int t = threadIdx.x, lane = t & 31, w = t >> 5;
    int g = lane >> 2, tq = lane & 3;
    int tileBase = blockIdx.x * 128;
    int mb = (w & 3) * 32, nb = (w >> 2) * 32;

    // ---- A conversion: 128 rows x 256 cols fp32 -> bf16 hi/lo in smem ----
    {
        int r = t >> 1;
        int half = (t & 1) * 128;
        int node = tileBase + r;
        bool v = node < N_NODES;
        const float* arow = g_aggr + (size_t)node * 256 + half;
        uint32_t* dhi = (uint32_t*)(sAhi + r * SA_STRIDE + half);
        uint32_t* dlo = (uint32_t*)(sAlo + r * SA_STRIDE + half);
#pragma unroll 4
        for (int c = 0; c < 128; c += 2) {
            float2 p = v ? *(const float2*)&arow[c] : make_float2(0.f, 0.f);
            __nv_bfloat162 ph, pl;
            ph.x = __float2bfloat16(p.x);
            pl.x = __float2bfloat16(p.x - __bfloat162float(ph.x));
            ph.y = __float2bfloat16(p.y);
            pl.y = __float2bfloat16(p.y - __bfloat162float(ph.y));
            dhi[c >> 1] = *(uint32_t*)&ph;
            dlo[c >> 1] = *(uint32_t*)&pl;
        }
    }

    float acc[2][4][3][4];
#pragma unroll
    for (int mi = 0; mi < 2; mi++)
#pragma unroll
        for (int q = 0; q < 4; q++)
#pragma unroll
            for (int p = 0; p < 3; p++)
#pragma unroll
                for (int i = 0; i < 4; i++) acc[mi][q][p][i] = 0.f;

    const __nv_bfloat16* gwhi = g_Whi[layer];
    const __nv_bfloat16* gwlo = g_Wlo[layer];

    for (int kc = 0; kc < 256; kc += 64) {
        __syncthreads();   // A ready (first iter) / previous chunk's mma reads done
        for (int idx = t; idx < 1536; idx += 256) {
            int j = idx >> 3, kk = (idx & 7) * 8;
            *(float4*)&sWhi[j * SW_STRIDE + kk] = *(const float4*)&gwhi[j * 256 + kc + kk];
            *(float4*)&sWlo[j * SW_STRIDE + kk] = *(const float4*)&gwlo[j * 256 + kc + kk];
        }
        __syncthreads();
#pragma unroll
        for (int pass = 0; pass < 3; pass++) {
            const __nv_bfloat16* A = (pass == 2) ? sAlo : sAhi;
            const __nv_bfloat16* B = (pass == 1) ? sWlo : sWhi;
#pragma unroll
            for (int ks = 0; ks < 4; ks++) {
                int ka = kc + ks * 16 + 2 * tq;
                int kw = ks * 16 + 2 * tq;
                uint32_t a[2][4];
#pragma unroll
                for (int mi = 0; mi < 2; mi++) {
                    const __nv_bfloat16* ar0 = A + (mb + mi * 16 + g) * SA_STRIDE + ka;
                    const __nv_bfloat16* ar1 = ar0 + 8 * SA_STRIDE;
                    a[mi][0] = *(const uint32_t*)ar0;
                    a[mi][1] = *(const uint32_t*)ar1;
                    a[mi][2] = *(const uint32_t*)(ar0 + 8);
                    a[mi][3] = *(const uint32_t*)(ar1 + 8);
                }
#pragma unroll
                for (int q = 0; q < 4; q++)
#pragma unroll
                    for (int p = 0; p < 3; p++) {
                        const __nv_bfloat16* br = B + (nb + q * 8 + p * 64 + g) * SW_STRIDE + kw;
                        uint32_t b0 = *(const uint32_t*)br;
                        uint32_t b1 = *(const uint32_t*)(br + 8);
                        mma_bf16(acc[0][q][p], a[0][0], a[0][1], a[0][2], a[0][3], b0, b1);
                        mma_bf16(acc[1][q][p], a[1][0], a[1][1], a[1][2], a[1][3], b0, b1);
                    }
            }
        }
    }
    __syncthreads();   // all mma done; sA region reusable

    // ---- epilogue: per-node combine in registers, write h^T ----
#pragma unroll
    for (int mi = 0; mi < 2; mi++)
#pragma unroll
        for (int h = 0; h < 2; h++) {
            int r = mb + mi * 16 + h * 8 + g;
            int node = tileBase + r;
            bool valid = node < N_NODES;
            float cnt = valid ? (float)g_deg[node] : 1.f;
            float s1 = cnt * (1.f / DELTA_C);
            float s2 = DELTA_C / cnt;
#pragma unroll
            for (int q = 0; q < 4; q++) {
                int c0 = nb + q * 8 + 2 * tq;
                float f0 = acc[mi][q][0][2 * h] + s1 * acc[mi][q][1][2 * h]
                         + s2 * acc[mi][q][2][2 * h] + mlpb[c0];
                float f1 = acc[mi][q][0][2 * h + 1] + s1 * acc[mi][q][1][2 * h + 1]
                         + s2 * acc[mi][q][2][2 * h + 1] + mlpb[c0 + 1];
                if (valid) {
                    float2 xv = *(const float2*)&x[node * 64 + c0];
                    f0 += xv.x;
                    f1 += xv.y;
                }
                sHT[c0 * 128 + r] = f0;
                sHT[(c0 + 1) * 128 + r] = f1;
            }
        }

    for (int i = t; i < 1024; i += 256)
        ((float4*)sWT)[i] = ((const float4*)g_W1T[layer])[i];
    if (t < 128) scol[t] = 0.f;
    __syncthreads();

    int ng = t & 15, og = t >> 4;

    // ---- phase 2: t1 = relu(W1 h + b1) ----
#pragma unroll
    for (int half = 0; half < 2; half++) {
        int nlb = half * 64 + (ng << 2);
        unsigned long long tacc[4][2];
#pragma unroll
        for (int i = 0; i < 4; i++) { tacc[i][0] = 0ULL; tacc[i][1] = 0ULL; }
#pragma unroll 4
        for (int k = 0; k < 64; k++) {
            float4 av = *(const float4*)&sHT[k * 128 + nlb];
            unsigned long long ap[4] = {pk2(av.x), pk2(av.y), pk2(av.z), pk2(av.w)};
            ulonglong2 bq = *(const ulonglong2*)&sWT[k * 64 + (og << 2)];
#pragma unroll
            for (int ni = 0; ni < 4; ni++) {
                tacc[ni][0] = fma2(ap[ni], bq.x, tacc[ni][0]);
                tacc[ni][1] = fma2(ap[ni], bq.y, tacc[ni][1]);
            }
        }
#pragma unroll
        for (int ni = 0; ni < 4; ni++)
#pragma unroll
            for (int j = 0; j < 2; j++) {
                float2 v = up2(tacc[ni][j]);
                int o = (og << 2) + 2 * j;
                sTT[o * 128 + nlb + ni] = fmaxf(v.x + b1v[o], 0.f);
                sTT[(o + 1) * 128 + nlb + ni] = fmaxf(v.y + b1v[o + 1], 0.f);
            }
    }
    __syncthreads();
    for (int i = t; i < 1024; i += 256)
        ((float4*)sWT)[i] = ((const float4*)g_W2T[layer])[i];
    __syncthreads();

    // ---- phase 3: out = relu(W2 t1 + b2) + BN stats ----
    float csum[4] = {0.f, 0.f, 0.f, 0.f};
    float csq[4]  = {0.f, 0.f, 0.f, 0.f};
#pragma unroll
    for (int half = 0; half < 2; half++) {
        int nlb = half * 64 + (ng << 2);
        unsigned long long oacc[4][2];
#pragma unroll
        for (int i = 0; i < 4; i++) { oacc[i][0] = 0ULL; oacc[i][1] = 0ULL; }
#pragma unroll 4
        for (int k = 0; k < 64; k++) {
            float4 av = *(const float4*)&sTT[k * 128 + nlb];
            unsigned long long ap[4] = {pk2(av.x), pk2(av.y), pk2(av.z), pk2(av.w)};
            ulonglong2 bq = *(const ulonglong2*)&sWT[k * 64 + (og << 2)];
#pragma unroll
            for (int ni = 0; ni < 4; ni++) {
                oacc[ni][0] = fma2(ap[ni], bq.x, oacc[ni][0]);
                oacc[ni][1] = fma2(ap[ni], bq.y, oacc[ni][1]);
            }
        }
#pragma unroll
        for (int ni = 0; ni < 4; ni++) {
            int node = tileBase + nlb + ni;
            if (node >= N_NODES) continue;
            float2 p0 = up2(oacc[ni][0]);
            float2 p1 = up2(oacc[ni][1]);
            float4 v;
            v.x = fmaxf(p0.x + b2v[(og << 2) + 0], 0.f);
            v.y = fmaxf(p0.y + b2v[(og << 2) + 1], 0.f);
            v.z = fmaxf(p1.x + b2v[(og << 2) + 2], 0.f);
            v.w = fmaxf(p1.y + b2v[(og << 2) + 3], 0.f);
            *(float4*)&out[node * 64 + (og << 2)] = v;
            csum[0] += v.x; csum[1] += v.y; csum[2] += v.z; csum[3] += v.w;
            csq[0] = fmaf(v.x, v.x, csq[0]); csq[1] = fmaf(v.y, v.y, csq[1]);
            csq[2] = fmaf(v.z, v.z, csq[2]); csq[3] = fmaf(v.w, v.w, csq[3]);
        }
    }
#pragma unroll
    for (int oi = 0; oi < 4; oi++) {
        atomicAdd(&scol[(og << 2) + oi], csum[oi]);
        atomicAdd(&scol[64 + (og << 2) + oi], csq[oi]);
    }
    __syncthreads();
    if (t < 64) atomicAdd(&g_colsum[t], scol[t]);
    else if (t < 128) atomicAdd(&g_colsq[t - 64], scol[t]);
}

// ---------------- batchnorm apply ----------------
__global__ void k_bn(float* __restrict__ xf, const float* __restrict__ gg,
                     const float* __restrict__ bb) {
    int i = blockIdx.x * blockDim.x + threadIdx.x;
    if (i >= N_NODES * 16) return;
    int c = (i & 15) << 2;
    float4 v = *(float4*)&xf[i * 4];
    float m0 = g_colsum[c] * (1.f / N_NODES), m1 = g_colsum[c + 1] * (1.f / N_NODES);
    float m2 = g_colsum[c + 2] * (1.f / N_NODES), m3 = g_colsum[c + 3] * (1.f / N_NODES);
    float s0 = gg[c] * rsqrtf(g_colsq[c] * (1.f / N_NODES) - m0 * m0 + BN_EPS);
    float s1 = gg[c + 1] * rsqrtf(g_colsq[c + 1] * (1.f / N_NODES) - m1 * m1 + BN_EPS);
    float s2 = gg[c + 2] * rsqrtf(g_colsq[c + 2] * (1.f / N_NODES) - m2 * m2 + BN_EPS);
    float s3 = gg[c + 3] * rsqrtf(g_colsq[c + 3] * (1.f / N_NODES) - m3 * m3 + BN_EPS);
    v.x = (v.x - m0) * s0 + bb[c];
    v.y = (v.y - m1) * s1 + bb[c + 1];
    v.z = (v.z - m2) * s2 + bb[c + 2];
    v.w = (v.w - m3) * s3 + bb[c + 3];
    *(float4*)&xf[i * 4] = v;
}

// ---------------- pooling ----------------
__global__ __launch_bounds__(256) void k_pool(const float* __restrict__ x,
                                              const int* __restrict__ batch) {
    __shared__ float ps[N_GRAPHS * 64];
    int t = threadIdx.x;
    for (int i = t; i < N_GRAPHS * 64; i += 256) ps[i] = 0.f;
    __syncthreads();

    const int CHUNK = (N_NODES + 127) / 128;
    int start = blockIdx.x * CHUNK;
    int endn = min(start + CHUNK, N_NODES);

    int d = t & 63, r = t >> 6;
    float acc = 0.f; int curb = -1;
    for (int n = start + r; n < endn; n += 4) {
        int b = batch[n];
        if (b != curb) {
            if (curb >= 0) atomicAdd(&ps[curb * 64 + d], acc);
            curb = b; acc = 0.f;
        }
        acc += x[n * 64 + d];
    }
    if (curb >= 0) atomicAdd(&ps[curb * 64 + d], acc);
    __syncthreads();
    for (int i = t; i < N_GRAPHS * 64; i += 256)
        if (ps[i] != 0.f) atomicAdd(&g_pool[i], ps[i]);
}

// ---------------- head ----------------
__global__ __launch_bounds__(256) void k_head(const float* __restrict__ fc1W,
                                              const float* __restrict__ fc1b,
                                              const float* __restrict__ fc2W,
                                              const float* __restrict__ fc2b,
                                              float* __restrict__ out) {
    __shared__ float sT1[64 * 64];
    __shared__ float sT2[64 * 32];
    int t = threadIdx.x;
    for (int i = t; i < 4096; i += 256) {
        int gi = i >> 6, o = i & 63;
        float acc = fc1b[o];
        for (int k = 0; k < 64; k++) acc = fmaf(g_pool[gi * 64 + k], fc1W[o * 64 + k], acc);
        sT1[i] = fmaxf(acc, 0.f);
    }
    __syncthreads();
    for (int i = t; i < 2048; i += 256) {
        int gi = i >> 5, o = i & 31;
        float acc = fc2b[o];
        for (int k = 0; k < 64; k++) acc = fmaf(sT1[gi * 64 + k], fc2W[o * 64 + k], acc);
        sT2[i] = acc;
    }
    __syncthreads();
    int w = t >> 5, lane = t & 31;
    for (int gi = w; gi < 64; gi += 8) {
        float v = sT2[gi * 32 + lane];
        float mx = v;
        for (int o = 16; o > 0; o >>= 1) mx = fmaxf(mx, __shfl_xor_sync(0xffffffffu, mx, o));
        float e = expf(v - mx);
        float s = e;
        for (int o = 16; o > 0; o >>= 1) s += __shfl_xor_sync(0xffffffffu, s, o);
        out[gi * 32 + lane] = v - mx - logf(s);
    }
}

// ---------------- launch ----------------
// input order: 0:x 1:edge_index 2:batch | 3..8 c1 | 9..14 c2 | 15..20 c3 |
//              21..26 bn1_g,bn1_b,bn2_g,bn2_b,bn3_g,bn3_b | 27..30 fc
extern "C" void kernel_launch(void* const* d_in, const int* in_sizes, int n_in,
                              void* d_out, int out_size) {
    const float* x = (const float*)d_in[0];
    const int* ei = (const int*)d_in[1];
    const int* src = ei;
    const int* dst = ei + N_EDGES;
    const int* batch = (const int*)d_in[2];
    float* out = (float*)d_out;

    float *featA = nullptr, *featB = nullptr;
    cudaGetSymbolAddress((void**)&featA, g_featA);
    cudaGetSymbolAddress((void**)&featB, g_featB);

    cudaFuncSetAttribute(k_mlp, cudaFuncAttributeMaxDynamicSharedMemorySize, MLP_SMEM);

    k_zero_deg<<<(N_NODES + 255) / 256, 256>>>();
    k_count<<<(N_EDGES + 255) / 256, 256>>>(dst);
    k_scan_blk<<<NB_SCAN, 1024>>>();
    k_scan_top<<<1, 64>>>();
    k_scan_add<<<(N_NODES + 256) / 256, 256>>>();
    k_fill<<<(N_EDGES + 255) / 256, 256>>>(src, dst);

    for (int L = 0; L < 3; L++)
        k_prep<<<192, 256>>>((const float*)d_in[3 + 6 * L],
                             (const float*)d_in[5 + 6 * L],
                             (const float*)d_in[7 + 6 * L], L);

    const float* cur = x;
    float* nxt = featA;
    for (int L = 0; L < 3; L++) {
        k_aggr<<<(N_NODES * 32 + 255) / 256, 256>>>(cur);
        k_mlp<<<(N_NODES + 127) / 128, 256, MLP_SMEM>>>(cur,
                                            (const float*)d_in[4 + 6 * L],
                                            (const float*)d_in[6 + 6 * L],
                                            (const float*)d_in[8 + 6 * L],
                                            nxt, L);
        k_bn<<<(N_NODES * 16 + 255) / 256, 256>>>(nxt,
                                                  (const float*)d_in[21 + 2 * L],
                                                  (const float*)d_in[22 + 2 * L]);
        cur = nxt;
        nxt = (nxt == featA) ? featB : featA;
    }

    k_pool<<<128, 256>>>(cur, batch);
    k_head<<<1, 256>>>((const float*)d_in[27], (const float*)d_in[28],
                       (const float*)d_in[29], (const float*)d_in[30], out);
}

// round 6
// speedup vs baseline: 1.4954x; 1.0627x over previous
#include <cuda_runtime.h>
#include <cuda_bf16.h>
#include <math.h>
#include <stdint.h>

#define N_NODES 50000
#define N_EDGES 1600000
#define N_GRAPHS 64
#define DELTA_C 2.5749f
#define BN_EPS 1e-5f
#define NB_SCAN 49

// ---------------- scratch ----------------
__device__ float g_featA[N_NODES * 64];
__device__ float g_featB[N_NODES * 64];
__device__ __nv_bfloat16 g_aggrHi[(size_t)N_NODES * 256];
__device__ __nv_bfloat16 g_aggrLo[(size_t)N_NODES * 256];
__device__ int   g_deg[N_NODES];
__device__ int   g_rowptr[N_NODES + 1];
__device__ int   g_cursor[N_NODES];
__device__ int   g_csrc[N_EDGES];
__device__ int   g_blksum[64];
__device__ int   g_blkoff[64];
__device__ __nv_bfloat16 g_Whi[3][192 * 256];   // [p*64+o][k]
__device__ __nv_bfloat16 g_Wlo[3][192 * 256];
__device__ float g_W1T[3][64 * 64];
__device__ float g_W2T[3][64 * 64];
__device__ float g_colsum[3][64];
__device__ float g_colsq[3][64];
__device__ float g_pool[N_GRAPHS * 64];

// smem layout for k_mlp (dynamic):
#define SA_STRIDE 264
#define SW_STRIDE 72
#define AHI_OFF 0                  // 128*264*2 = 67584
#define ALO_OFF 67584
#define WHI_OFF 135168             // 192*72*2 = 27648
#define WLO_OFF 162816
#define MLP_SMEM 190464
// phase-2/3 overlay (dead A region):
#define HT_OFF 0
#define TT_OFF 32768
#define WT_OFF 65536
#define SCOL_OFF 81920

// ---------------- f32x2 helpers ----------------
__device__ __forceinline__ unsigned long long pk2(float x) {
    unsigned long long r;
    asm("mov.b64 %0, {%1,%1};" : "=l"(r) : "f"(x));
    return r;
}
__device__ __forceinline__ unsigned long long fma2(unsigned long long a,
                                                   unsigned long long b,
                                                   unsigned long long c) {
    unsigned long long d;
    asm("fma.rn.f32x2 %0, %1, %2, %3;" : "=l"(d) : "l"(a), "l"(b), "l"(c));
    return d;
}
__device__ __forceinline__ float2 up2(unsigned long long v) {
    float2 f;
    asm("mov.b64 {%0,%1}, %2;" : "=f"(f.x), "=f"(f.y) : "l"(v));
    return f;
}

// ---------------- warp mma ----------------
__device__ __forceinline__ void mma_bf16(float* acc, uint32_t a0, uint32_t a1,
                                         uint32_t a2, uint32_t a3,
                                         uint32_t b0, uint32_t b1) {
    asm volatile("mma.sync.aligned.m16n8k16.row.col.f32.bf16.bf16.f32 "
        "{%0,%1,%2,%3}, {%4,%5,%6,%7}, {%8,%9}, {%0,%1,%2,%3};"
        : "+f"(acc[0]), "+f"(acc[1]), "+f"(acc[2]), "+f"(acc[3])
        : "r"(a0), "r"(a1), "r"(a2), "r"(a3), "r"(b0), "r"(b1));
}

__device__ __forceinline__ __nv_bfloat162 bf16_split(float a, float b,
                                                     __nv_bfloat162& lo) {
    __nv_bfloat162 hi;
    hi.x = __float2bfloat16(a);
    hi.y = __float2bfloat16(b);
    lo.x = __float2bfloat16(a - __bfloat162float(hi.x));
    lo.y = __float2bfloat16(b - __bfloat162float(hi.y));
    return hi;
}

// ---------------- CSR build ----------------
__global__ void k_zero_deg() {
    int i = blockIdx.x * blockDim.x + threadIdx.x;
    if (i < N_NODES) g_deg[i] = 0;
}
__global__ void k_count(const int* __restrict__ dst) {
    int e = blockIdx.x * blockDim.x + threadIdx.x;
    if (e < N_EDGES) atomicAdd(&g_deg[dst[e]], 1);
}
__global__ void k_scan_blk() {
    __shared__ int s[1024];
    int t = threadIdx.x;
    int idx = blockIdx.x * 1024 + t;
    int v = (idx < N_NODES) ? g_deg[idx] : 0;
    s[t] = v;
    __syncthreads();
    for (int d = 1; d < 1024; d <<= 1) {
        int add = (t >= d) ? s[t - d] : 0;
        __syncthreads();
        s[t] += add;
        __syncthreads();
    }
    if (idx < N_NODES) g_rowptr[idx + 1] = s[t];
    if (t == 1023) g_blksum[blockIdx.x] = s[1023];
}
__global__ void k_scan_top() {
    __shared__ int s[64];
    int t = threadIdx.x;
    int v = (t < NB_SCAN) ? g_blksum[t] : 0;
    s[t] = v;
    __syncthreads();
    for (int d = 1; d < 64; d <<= 1) {
        int add = (t >= d) ? s[t - d] : 0;
        __syncthreads();
        s[t] += add;
        __syncthreads();
    }
    g_blkoff[t] = s[t] - v;
}
__global__ void k_scan_add() {
    int idx = blockIdx.x * blockDim.x + threadIdx.x;
    if (idx < N_NODES) {
        int r = g_rowptr[idx + 1] + g_blkoff[idx >> 10];
        g_rowptr[idx + 1] = r;
        g_cursor[idx] = r - g_deg[idx];
    }
    if (idx == 0) g_rowptr[0] = 0;
    if (idx < N_GRAPHS * 64) g_pool[idx] = 0.f;
    if (idx < 192) {                       // zero all 3 layers' BN stats
        g_colsum[idx >> 6][idx & 63] = 0.f;
        g_colsq[idx >> 6][idx & 63] = 0.f;
    }
}
__global__ void k_fill(const int* __restrict__ src, const int* __restrict__ dst) {
    int e = blockIdx.x * blockDim.x + threadIdx.x;
    if (e < N_EDGES) {
        int p = atomicAdd(&g_cursor[dst[e]], 1);
        g_csrc[p] = src[e];
    }
}

// ---------------- weight prep ----------------
__global__ void k_prep(const float* __restrict__ mlpW, const float* __restrict__ W1,
                       const float* __restrict__ W2, int layer) {
    int i = blockIdx.x * blockDim.x + threadIdx.x;
    if (i < 192 * 256) {
        int j = i >> 8, k = i & 255;
        int p = j >> 6, o = j & 63;
        float w = mlpW[o * 768 + p * 256 + k];
        __nv_bfloat16 hi = __float2bfloat16(w);
        __nv_bfloat16 lo = __float2bfloat16(w - __bfloat162float(hi));
        g_Whi[layer][i] = hi;
        g_Wlo[layer][i] = lo;
    }
    if (i < 4096) {
        int k = i >> 6, o = i & 63;
        g_W1T[layer][i] = W1[o * 64 + k];
        g_W2T[layer][i] = W2[o * 64 + k];
    }
}

// ---------------- aggregation: warp/node CSR gather, fused BN affine, bf16-split out ----
// For layer>0: input xf is the raw (pre-BN) previous-layer output; apply
// y = a*x + b per feature with a,b from prev layer stats + gamma/beta.
__global__ __launch_bounds__(256) void k_aggr(const float* __restrict__ xf,
                                              const float* __restrict__ gg,
                                              const float* __restrict__ bb,
                                              int prevLayer) {
    int warp = (blockIdx.x * blockDim.x + threadIdx.x) >> 5;
    int lane = threadIdx.x & 31;
    if (warp >= N_NODES) return;

    float a0 = 1.f, b0 = 0.f, a1 = 1.f, b1 = 0.f;
    if (gg) {
        int c = 2 * lane;
        float m = g_colsum[prevLayer][c] * (1.f / N_NODES);
        float vv = g_colsq[prevLayer][c] * (1.f / N_NODES) - m * m;
        a0 = gg[c] * rsqrtf(vv + BN_EPS);
        b0 = bb[c] - m * a0;
        m = g_colsum[prevLayer][c + 1] * (1.f / N_NODES);
        vv = g_colsq[prevLayer][c + 1] * (1.f / N_NODES) - m * m;
        a1 = gg[c + 1] * rsqrtf(vv + BN_EPS);
        b1 = bb[c + 1] - m * a1;
    }

    int beg = g_rowptr[warp];
    int end = g_rowptr[warp + 1];

    float s0 = 0.f, s1 = 0.f, q0 = 0.f, q1 = 0.f;
    float m0 = -INFINITY, m1 = -INFINITY;

    int j = beg;
    for (; j + 32 <= end; j += 32) {
        int e = g_csrc[j + lane];
#pragma unroll
        for (int i = 0; i < 32; i++) {
            int sidx = __shfl_sync(0xffffffffu, e, i);
            float2 v = *(const float2*)&xf[sidx * 64 + 2 * lane];
            float v0 = fmaf(v.x, a0, b0);
            float v1 = fmaf(v.y, a1, b1);
            s0 += v0; s1 += v1;
            q0 = fmaf(v0, v0, q0); q1 = fmaf(v1, v1, q1);
            m0 = fmaxf(m0, v0); m1 = fmaxf(m1, v1);
        }
    }
    int nrem = end - j;
    if (nrem > 0) {
        int e = (lane < nrem) ? g_csrc[j + lane] : 0;
        for (int i = 0; i < nrem; i++) {
            int sidx = __shfl_sync(0xffffffffu, e, i);
            float2 v = *(const float2*)&xf[sidx * 64 + 2 * lane];
            float v0 = fmaf(v.x, a0, b0);
            float v1 = fmaf(v.y, a1, b1);
            s0 += v0; s1 += v1;
            q0 = fmaf(v0, v0, q0); q1 = fmaf(v1, v1, q1);
            m0 = fmaxf(m0, v0); m1 = fmaxf(m1, v1);
        }
    }

    float cnt = (float)(end - beg);
    float inv = 1.0f / cnt;
    float mean0 = s0 * inv, mean1 = s1 * inv;
    float var0 = fmaxf(q0 * inv - mean0 * mean0, 0.f);
    float var1 = fmaxf(q1 * inv - mean1 * mean1, 0.f);

    // bf16 hi/lo split, write planes: cols [sums | maxs | means | var]
    __nv_bfloat16* ah = g_aggrHi + (size_t)warp * 256;
    __nv_bfloat16* al = g_aggrLo + (size_t)warp * 256;
    __nv_bfloat162 lo, hi;
    hi = bf16_split(s0, s1, lo);
    *(__nv_bfloat162*)&ah[2 * lane] = hi;       *(__nv_bfloat162*)&al[2 * lane] = lo;
    hi = bf16_split(m0, m1, lo);
    *(__nv_bfloat162*)&ah[64 + 2 * lane] = hi;  *(__nv_bfloat162*)&al[64 + 2 * lane] = lo;
    hi = bf16_split(mean0, mean1, lo);
    *(__nv_bfloat162*)&ah[128 + 2 * lane] = hi; *(__nv_bfloat162*)&al[128 + 2 * lane] = lo;
    hi = bf16_split(var0, var1, lo);
    *(__nv_bfloat162*)&ah[192 + 2 * lane] = hi; *(__nv_bfloat162*)&al[192 + 2 * lane] = lo;
}

// ---------------- fused MLP: mma.sync phase1 + f32x2 phases 2/3 ----------------
__global__ __launch_bounds__(256) void k_mlp(const float* __restrict__ x,
                                             const float* __restrict__ mlpb,
                                             const float* __restrict__ b1v,
                                             const float* __restrict__ b2v,
                                             float* __restrict__ out, int layer,
                                             const float* __restrict__ ggP,
                                             const float* __restrict__ bbP) {
    extern __shared__ __align__(16) char smem[];
    __nv_bfloat16* sAhi = (__nv_bfloat16*)(smem + AHI_OFF);
    __nv_bfloat16* sAlo = (__nv_bfloat16*)(smem + ALO_OFF);
    __nv_bfloat16* sWhi = (__nv_bfloat16*)(smem + WHI_OFF);
    __nv_bfloat16* sWlo = (__nv_bfloat16*)(smem + WLO_OFF);
    float* sHT  = (float*)(smem + HT_OFF);
    float* sTT  = (float*)(smem + TT_OFF);
    float* sWT  = (float*)(smem + WT_OFF);
    float* scol = (float*)(smem + SCOL_OFF);

    int t = threadIdx.x, lane = t & 31, w = t >> 5;
    int g = lane >> 2, tq = lane & 3;
    int tileBase = blockIdx.x * 128;
    int mb = (w & 3) * 32, nb = (w >> 2) * 32;

    // ---- A copy: pre-split planes -> smem ----
    {
        int r = t >> 1;
        int half = (t & 1) * 128;
        int node = tileBase + r;
        uint4* dHi = (uint4*)(sAhi + r * SA_STRIDE + half);
        uint4* dLo = (uint4*)(sAlo + r * SA_STRIDE + half);
        if (node < N_NODES) {
            const uint4* sHi = (const uint4*)(g_aggrHi + (size_t)node * 256 + half);
            const uint4* sLo = (const uint4*)(g_aggrLo + (size_t)node * 256 + half);
#pragma unroll
            for (int c = 0; c < 16; c++) { dHi[c] = sHi[c]; dLo[c] = sLo[c]; }
        } else {
            uint4 z = make_uint4(0, 0, 0, 0);
#pragma unroll
            for (int c = 0; c < 16; c++) { dHi[c] = z; dLo[c] = z; }
        }
    }

    float acc[2][4][3][4];
#pragma unroll
    for (int mi = 0; mi < 2; mi++)
#pragma unroll
        for (int q = 0; q < 4; q++)
#pragma unroll
            for (int p = 0; p < 3; p++)
#pragma unroll
                for (int i = 0; i < 4; i++) acc[mi][q][p][i] = 0.f;

    const __nv_bfloat16* gwhi = g_Whi[layer];
    const __nv_bfloat16* gwlo = g_Wlo[layer];

    for (int kc = 0; kc < 256; kc += 64) {
        __syncthreads();
        for (int idx = t; idx < 1536; idx += 256) {
            int j = idx >> 3, kk = (idx & 7) * 8;
            *(float4*)&sWhi[j * SW_STRIDE + kk] = *(const float4*)&gwhi[j * 256 + kc + kk];
            *(float4*)&sWlo[j * SW_STRIDE + kk] = *(const float4*)&gwlo[j * 256 + kc + kk];
        }
        __syncthreads();
#pragma unroll
        for (int pass = 0; pass < 3; pass++) {
            const __nv_bfloat16* A = (pass == 2) ? sAlo : sAhi;
            const __nv_bfloat16* B = (pass == 1) ? sWlo : sWhi;
#pragma unroll
            for (int ks = 0; ks < 4; ks++) {
                int ka = kc + ks * 16 + 2 * tq;
                int kw = ks * 16 + 2 * tq;
                uint32_t a[2][4];
#pragma unroll
                for (int mi = 0; mi < 2; mi++) {
                    const __nv_bfloat16* ar0 = A + (mb + mi * 16 + g) * SA_STRIDE + ka;
                    const __nv_bfloat16* ar1 = ar0 + 8 * SA_STRIDE;
                    a[mi][0] = *(const uint32_t*)ar0;
                    a[mi][1] = *(const uint32_t*)ar1;
                    a[mi][2] = *(const uint32_t*)(ar0 + 8);
                    a[mi][3] = *(const uint32_t*)(ar1 + 8);
                }
#pragma unroll
                for (int q = 0; q < 4; q++)
#pragma unroll
                    for (int p = 0; p < 3; p++) {
                        const __nv_bfloat16* br = B + (nb + q * 8 + p * 64 + g) * SW_STRIDE + kw;
                        uint32_t b0 = *(const uint32_t*)br;
                        uint32_t b1 = *(const uint32_t*)(br + 8);
                        mma_bf16(acc[0][q][p], a[0][0], a[0][1], a[0][2], a[0][3], b0, b1);
                        mma_bf16(acc[1][q][p], a[1][0], a[1][1], a[1][2], a[1][3], b0, b1);
                    }
            }
        }
    }
    __syncthreads();

    // ---- residual BN affine (layer>0) ----
    float ra[4][2], rb[4][2];
#pragma unroll
    for (int q = 0; q < 4; q++)
#pragma unroll
        for (int j = 0; j < 2; j++) {
            float a = 1.f, b = 0.f;
            if (ggP) {
                int c = nb + q * 8 + 2 * tq + j;
                float m = g_colsum[layer - 1][c] * (1.f / N_NODES);
                float vv = g_colsq[layer - 1][c] * (1.f / N_NODES) - m * m;
                a = ggP[c] * rsqrtf(vv + BN_EPS);
                b = bbP[c] - m * a;
            }
            ra[q][j] = a; rb[q][j] = b;
        }

    // ---- epilogue: per-node combine, write h^T ----
#pragma unroll
    for (int mi = 0; mi < 2; mi++)
#pragma unroll
        for (int h = 0; h < 2; h++) {
            int r = mb + mi * 16 + h * 8 + g;
            int node = tileBase + r;
            bool valid = node < N_NODES;
            float cnt = valid ? (float)g_deg[node] : 1.f;
            float s1 = cnt * (1.f / DELTA_C);
            float s2 = DELTA_C / cnt;
#pragma unroll
            for (int q = 0; q < 4; q++) {
                int c0 = nb + q * 8 + 2 * tq;
                float f0 = acc[mi][q][0][2 * h] + s1 * acc[mi][q][1][2 * h]
                         + s2 * acc[mi][q][2][2 * h] + mlpb[c0];
                float f1 = acc[mi][q][0][2 * h + 1] + s1 * acc[mi][q][1][2 * h + 1]
                         + s2 * acc[mi][q][2][2 * h + 1] + mlpb[c0 + 1];
                if (valid) {
                    float2 xv = *(const float2*)&x[node * 64 + c0];
                    f0 += fmaf(xv.x, ra[q][0], rb[q][0]);
                    f1 += fmaf(xv.y, ra[q][1], rb[q][1]);
                }
                sHT[c0 * 128 + r] = f0;
                sHT[(c0 + 1) * 128 + r] = f1;
            }
        }

    for (int i = t; i < 1024; i += 256)
        ((float4*)sWT)[i] = ((const float4*)g_W1T[layer])[i];
    if (t < 128) scol[t] = 0.f;
    __syncthreads();

    int ng = t & 15, og = t >> 4;

    // ---- phase 2: t1 = relu(W1 h + b1) ----
#pragma unroll
    for (int half = 0; half < 2; half++) {
        int nlb = half * 64 + (ng << 2);
        unsigned long long tacc[4][2];
#pragma unroll
        for (int i = 0; i < 4; i++) { tacc[i][0] = 0ULL; tacc[i][1] = 0ULL; }
#pragma unroll 4
        for (int k = 0; k < 64; k++) {
            float4 av = *(const float4*)&sHT[k * 128 + nlb];
            unsigned long long ap[4] = {pk2(av.x), pk2(av.y), pk2(av.z), pk2(av.w)};
            ulonglong2 bq = *(const ulonglong2*)&sWT[k * 64 + (og << 2)];
#pragma unroll
            for (int ni = 0; ni < 4; ni++) {
                tacc[ni][0] = fma2(ap[ni], bq.x, tacc[ni][0]);
                tacc[ni][1] = fma2(ap[ni], bq.y, tacc[ni][1]);
            }
        }
#pragma unroll
        for (int ni = 0; ni < 4; ni++)
#pragma unroll
            for (int j = 0; j < 2; j++) {
                float2 v = up2(tacc[ni][j]);
                int o = (og << 2) + 2 * j;
                sTT[o * 128 + nlb + ni] = fmaxf(v.x + b1v[o], 0.f);
                sTT[(o + 1) * 128 + nlb + ni] = fmaxf(v.y + b1v[o + 1], 0.f);
            }
    }
    __syncthreads();
    for (int i = t; i < 1024; i += 256)
        ((float4*)sWT)[i] = ((const float4*)g_W2T[layer])[i];
    __syncthreads();

    // ---- phase 3: out = relu(W2 t1 + b2) + BN stats ----
    float csum[4] = {0.f, 0.f, 0.f, 0.f};
    float csq[4]  = {0.f, 0.f, 0.f, 0.f};
#pragma unroll
    for (int half = 0; half < 2; half++) {
        int nlb = half * 64 + (ng << 2);
        unsigned long long oacc[4][2];
#pragma unroll
        for (int i = 0; i < 4; i++) { oacc[i][0] = 0ULL; oacc[i][1] = 0ULL; }
#pragma unroll 4
        for (int k = 0; k < 64; k++) {
            float4 av = *(const float4*)&sTT[k * 128 + nlb];
            unsigned long long ap[4] = {pk2(av.x), pk2(av.y), pk2(av.z), pk2(av.w)};
            ulonglong2 bq = *(const ulonglong2*)&sWT[k * 64 + (og << 2)];
#pragma unroll
            for (int ni = 0; ni < 4; ni++) {
                oacc[ni][0] = fma2(ap[ni], bq.x, oacc[ni][0]);
                oacc[ni][1] = fma2(ap[ni], bq.y, oacc[ni][1]);
            }
        }
#pragma unroll
        for (int ni = 0; ni < 4; ni++) {
            int node = tileBase + nlb + ni;
            if (node >= N_NODES) continue;
            float2 p0 = up2(oacc[ni][0]);
            float2 p1 = up2(oacc[ni][1]);
            float4 v;
            v.x = fmaxf(p0.x + b2v[(og << 2) + 0], 0.f);
            v.y = fmaxf(p0.y + b2v[(og << 2) + 1], 0.f);
            v.z = fmaxf(p1.x + b2v[(og << 2) + 2], 0.f);
            v.w = fmaxf(p1.y + b2v[(og << 2) + 3], 0.f);
            *(float4*)&out[node * 64 + (og << 2)] = v;
            csum[0] += v.x; csum[1] += v.y; csum[2] += v.z; csum[3] += v.w;
            csq[0] = fmaf(v.x, v.x, csq[0]); csq[1] = fmaf(v.y, v.y, csq[1]);
            csq[2] = fmaf(v.z, v.z, csq[2]); csq[3] = fmaf(v.w, v.w, csq[3]);
        }
    }
#pragma unroll
    for (int oi = 0; oi < 4; oi++) {
        atomicAdd(&scol[(og << 2) + oi], csum[oi]);
        atomicAdd(&scol[64 + (og << 2) + oi], csq[oi]);
    }
    __syncthreads();
    if (t < 64) atomicAdd(&g_colsum[layer][t], scol[t]);
    else if (t < 128) atomicAdd(&g_colsq[layer][t - 64], scol[t]);
}

// ---------------- pooling (fused final BN affine) ----------------
__global__ __launch_bounds__(256) void k_pool(const float* __restrict__ x,
                                              const int* __restrict__ batch,
                                              const float* __restrict__ gg,
                                              const float* __restrict__ bb) {
    __shared__ float ps[N_GRAPHS * 64];
    int t = threadIdx.x;
    for (int i = t; i < N_GRAPHS * 64; i += 256) ps[i] = 0.f;
    __syncthreads();

    int d = t & 63, r = t >> 6;
    float m = g_colsum[2][d] * (1.f / N_NODES);
    float vv = g_colsq[2][d] * (1.f / N_NODES) - m * m;
    float a = gg[d] * rsqrtf(vv + BN_EPS);
    float b = bb[d] - m * a;

    const int CHUNK = (N_NODES + 127) / 128;
    int start = blockIdx.x * CHUNK;
    int endn = min(start + CHUNK, N_NODES);

    float acc = 0.f; int curb = -1;
    for (int n = start + r; n < endn; n += 4) {
        int bt = batch[n];
        if (bt != curb) {
            if (curb >= 0) atomicAdd(&ps[curb * 64 + d], acc);
            curb = bt; acc = 0.f;
        }
        acc += fmaf(x[n * 64 + d], a, b);
    }
    if (curb >= 0) atomicAdd(&ps[curb * 64 + d], acc);
    __syncthreads();
    for (int i = t; i < N_GRAPHS * 64; i += 256)
        if (ps[i] != 0.f) atomicAdd(&g_pool[i], ps[i]);
}

// ---------------- head ----------------
__global__ __launch_bounds__(256) void k_head(const float* __restrict__ fc1W,
                                              const float* __restrict__ fc1b,
                                              const float* __restrict__ fc2W,
                                              const float* __restrict__ fc2b,
                                              float* __restrict__ out) {
    __shared__ float sT1[64 * 64];
    __shared__ float sT2[64 * 32];
    int t = threadIdx.x;
    for (int i = t; i < 4096; i += 256) {
        int gi = i >> 6, o = i & 63;
        float acc = fc1b[o];
        for (int k = 0; k < 64; k++) acc = fmaf(g_pool[gi * 64 + k], fc1W[o * 64 + k], acc);
        sT1[i] = fmaxf(acc, 0.f);
    }
    __syncthreads();
    for (int i = t; i < 2048; i += 256) {
        int gi = i >> 5, o = i & 31;
        float acc = fc2b[o];
        for (int k = 0; k < 64; k++) acc = fmaf(sT1[gi * 64 + k], fc2W[o * 64 + k], acc);
        sT2[i] = acc;
    }
    __syncthreads();
    int w = t >> 5, lane = t & 31;
    for (int gi = w; gi < 64; gi += 8) {
        float v = sT2[gi * 32 + lane];
        float mx = v;
        for (int o = 16; o > 0; o >>= 1) mx = fmaxf(mx, __shfl_xor_sync(0xffffffffu, mx, o));
        float e = expf(v - mx);
        float s = e;
        for (int o = 16; o > 0; o >>= 1) s += __shfl_xor_sync(0xffffffffu, s, o);
        out[gi * 32 + lane] = v - mx - logf(s);
    }
}

// ---------------- launch ----------------
// input order: 0:x 1:edge_index 2:batch | 3..8 c1 | 9..14 c2 | 15..20 c3 |
//              21..26 bn1_g,bn1_b,bn2_g,bn2_b,bn3_g,bn3_b | 27..30 fc
extern "C" void kernel_launch(void* const* d_in, const int* in_sizes, int n_in,
                              void* d_out, int out_size) {
    const float* x = (const float*)d_in[0];
    const int* ei = (const int*)d_in[1];
    const int* src = ei;
    const int* dst = ei + N_EDGES;
    const int* batch = (const int*)d_in[2];
    float* out = (float*)d_out;

    float *featA = nullptr, *featB = nullptr;
    cudaGetSymbolAddress((void**)&featA, g_featA);
    cudaGetSymbolAddress((void**)&featB, g_featB);

    cudaFuncSetAttribute(k_mlp, cudaFuncAttributeMaxDynamicSharedMemorySize, MLP_SMEM);

    k_zero_deg<<<(N_NODES + 255) / 256, 256>>>();
    k_count<<<(N_EDGES + 255) / 256, 256>>>(dst);
    k_scan_blk<<<NB_SCAN, 1024>>>();
    k_scan_top<<<1, 64>>>();
    k_scan_add<<<(N_NODES + 256) / 256, 256>>>();
    k_fill<<<(N_EDGES + 255) / 256, 256>>>(src, dst);

    for (int L = 0; L < 3; L++)
        k_prep<<<192, 256>>>((const float*)d_in[3 + 6 * L],
                             (const float*)d_in[5 + 6 * L],
                             (const float*)d_in[7 + 6 * L], L);

    const float* cur = x;
    float* nxt = featA;
    for (int L = 0; L < 3; L++) {
        const float* ggP = (L > 0) ? (const float*)d_in[21 + 2 * (L - 1)] : nullptr;
        const float* bbP = (L > 0) ? (const float*)d_in[22 + 2 * (L - 1)] : nullptr;
        k_aggr<<<(N_NODES * 32 + 255) / 256, 256>>>(cur, ggP, bbP, L - 1);
        k_mlp<<<(N_NODES + 127) / 128, 256, MLP_SMEM>>>(cur,
                                            (const float*)d_in[4 + 6 * L],
                                            (const float*)d_in[6 + 6 * L],
                                            (const float*)d_in[8 + 6 * L],
                                            nxt, L, ggP, bbP);
        cur = nxt;
        nxt = (nxt == featA) ? featB : featA;
    }

    k_pool<<<128, 256>>>(cur, batch, (const float*)d_in[25], (const float*)d_in[26]);
    k_head<<<1, 256>>>((const float*)d_in[27], (const float*)d_in[28],
                       (const float*)d_in[29], (const float*)d_in[30], out);
}